// round 1
// baseline (speedup 1.0000x reference)
#include <cuda_runtime.h>
#include <math.h>

// Problem constants
#define B_TOT 16384
#define G_    8
#define S_    16
#define H_    512
#define TB    32      // batch rows per CTA
#define NT    256     // threads per CTA

// Dynamic smem layout:
//   hs: TB*H_ floats (activations, 64 KB)
//   ws: 512*33 floats (weight tile, padded stride, ~66 KB)
#define WS_OFF (TB * H_)
#define SMEM_FLOATS (TB * H_ + 512 * 33)

__device__ __forceinline__ float swish_act(float v, float sp) {
    // v * sigmoid(v * sp) / 1.1
    float e = __expf(-v * sp);
    float sig = __fdividef(1.0f, 1.0f + e);
    return v * sig * 0.9090909090909091f;
}

__global__ void __launch_bounds__(NT, 1) gmlp_fused_kernel(
    const float* __restrict__ x,
    const float* __restrict__ W1, const float* __restrict__ b1, const float* __restrict__ beta1,
    const float* __restrict__ W2, const float* __restrict__ b2, const float* __restrict__ beta2,
    const float* __restrict__ W3, const float* __restrict__ b3, const float* __restrict__ beta3,
    const float* __restrict__ W4, const float* __restrict__ b4,
    float* __restrict__ out)
{
    extern __shared__ float smem[];
    float* hs = smem;            // [TB][H_]
    float* ws = smem + WS_OFF;   // padded weight tile
    __shared__ float xs[TB * S_];

    const int tid = threadIdx.x;
    const int g   = blockIdx.y;
    const int b0  = blockIdx.x * TB;
    const int tx  = tid & 31;    // 0..31 -> output column group
    const int ty  = tid >> 5;    // 0..7  -> row group (rows ty, ty+8, ty+16, ty+24)

    // ---------------- load x tile [32 x 16] ----------------
    {
        int r = tid >> 4, s = tid & 15;  // 16 rows covered, do 2 halves
        xs[r * S_ + s]        = x[(size_t)(b0 + r) * (G_ * S_) + g * S_ + s];
        xs[(r + 16) * S_ + s] = x[(size_t)(b0 + r + 16) * (G_ * S_) + g * S_ + s];
    }
    // ---------------- load W1 [512 x 16] into ws (stride 17) ----------------
    {
        const float* Wg = W1 + (size_t)g * H_ * S_;
        #pragma unroll
        for (int l = 0; l < 8; ++l) {
            int chunk = tid + NT * l;        // 0..2047 float4 chunks
            int o = chunk >> 2, q = chunk & 3;
            float4 v = *(const float4*)(Wg + o * S_ + q * 4);
            float* dst = ws + o * 17 + q * 4;
            dst[0] = v.x; dst[1] = v.y; dst[2] = v.z; dst[3] = v.w;
        }
    }
    __syncthreads();

    float acc[4][16];

    // ---------------- layer 1: [32,16] x [512,16]^T -> [32,512] ----------------
    {
        #pragma unroll
        for (int j = 0; j < 4; ++j)
            #pragma unroll
            for (int i = 0; i < 16; ++i) acc[j][i] = 0.0f;

        #pragma unroll
        for (int k = 0; k < S_; ++k) {
            float hv[4];
            #pragma unroll
            for (int j = 0; j < 4; ++j) hv[j] = xs[(ty + 8 * j) * S_ + k];
            #pragma unroll
            for (int i = 0; i < 16; ++i) {
                float w = ws[(tx + 32 * i) * 17 + k];
                #pragma unroll
                for (int j = 0; j < 4; ++j) acc[j][i] = fmaf(hv[j], w, acc[j][i]);
            }
        }
        float sp = log1pf(__expf(beta1[g]));
        __syncthreads();  // everyone done reading ws/xs
        #pragma unroll
        for (int i = 0; i < 16; ++i) {
            int c = tx + 32 * i;
            float bb = b1[(size_t)g * H_ + c];
            #pragma unroll
            for (int j = 0; j < 4; ++j) {
                float v = acc[j][i] + bb;
                hs[(ty + 8 * j) * H_ + c] = swish_act(v, sp);
            }
        }
    }
    // (next layer's first __syncthreads orders hs writes before reads)

    // ---------------- layers 2 & 3: [32,512] x [512,512]^T ----------------
    for (int layer = 0; layer < 2; ++layer) {
        const float* Wg = (layer == 0 ? W2 : W3) + (size_t)g * H_ * H_;
        const float* bg = (layer == 0 ? b2 : b3) + (size_t)g * H_;
        float beta = (layer == 0 ? beta2[g] : beta3[g]);

        #pragma unroll
        for (int j = 0; j < 4; ++j)
            #pragma unroll
            for (int i = 0; i < 16; ++i) acc[j][i] = 0.0f;

        for (int kt = 0; kt < H_ / 32; ++kt) {
            __syncthreads();  // previous ws reads done (and hs writes visible at kt==0)
            // load W tile [512 x 32] into ws (stride 33)
            #pragma unroll
            for (int l = 0; l < 16; ++l) {
                int chunk = tid + NT * l;        // 0..4095 float4 chunks
                int o = chunk >> 3, q = chunk & 7;
                float4 v = *(const float4*)(Wg + (size_t)o * H_ + kt * 32 + q * 4);
                float* dst = ws + o * 33 + q * 4;
                dst[0] = v.x; dst[1] = v.y; dst[2] = v.z; dst[3] = v.w;
            }
            __syncthreads();

            #pragma unroll 2
            for (int kk = 0; kk < 32; ++kk) {
                float hv[4];
                #pragma unroll
                for (int j = 0; j < 4; ++j) hv[j] = hs[(ty + 8 * j) * H_ + kt * 32 + kk];
                #pragma unroll
                for (int i = 0; i < 16; ++i) {
                    float w = ws[(tx + 32 * i) * 33 + kk];
                    #pragma unroll
                    for (int j = 0; j < 4; ++j) acc[j][i] = fmaf(hv[j], w, acc[j][i]);
                }
            }
        }
        float sp = log1pf(__expf(beta));
        __syncthreads();  // everyone done reading hs before overwrite
        #pragma unroll
        for (int i = 0; i < 16; ++i) {
            int c = tx + 32 * i;
            float bb = bg[c];
            #pragma unroll
            for (int j = 0; j < 4; ++j) {
                float v = acc[j][i] + bb;
                hs[(ty + 8 * j) * H_ + c] = swish_act(v, sp);
            }
        }
    }

    // ---------------- layer 4: [32,512] x [16,512]^T -> [32,16] ----------------
    {
        const float* Wg = W4 + (size_t)g * S_ * H_;
        __syncthreads();  // hs writes visible, ws free to overwrite
        // load W4 [16 x 512] into ws (stride 513)
        #pragma unroll
        for (int l = 0; l < 8; ++l) {
            int chunk = tid + NT * l;            // 0..2047 float4 chunks
            int s = chunk >> 7, q = chunk & 127;
            float4 v = *(const float4*)(Wg + (size_t)s * H_ + q * 4);
            float* dst = ws + s * 513 + q * 4;
            dst[0] = v.x; dst[1] = v.y; dst[2] = v.z; dst[3] = v.w;
        }
        __syncthreads();

        int s  = tid & 15;
        int r0 = tid >> 4;           // 0..15; also handles r0+16
        float a0 = 0.0f, a1 = 0.0f;
        #pragma unroll 8
        for (int k = 0; k < H_; ++k) {
            float w = ws[s * 513 + k];
            a0 = fmaf(hs[r0 * H_ + k],        w, a0);
            a1 = fmaf(hs[(r0 + 16) * H_ + k], w, a1);
        }
        float bb = b4[(size_t)g * S_ + s];
        out[(size_t)(b0 + r0) * (G_ * S_)      + g * S_ + s] = a0 + bb;
        out[(size_t)(b0 + r0 + 16) * (G_ * S_) + g * S_ + s] = a1 + bb;
    }
}

extern "C" void kernel_launch(void* const* d_in, const int* in_sizes, int n_in,
                              void* d_out, int out_size) {
    const float* x     = (const float*)d_in[0];
    const float* W1    = (const float*)d_in[1];
    const float* b1    = (const float*)d_in[2];
    const float* beta1 = (const float*)d_in[3];
    const float* W2    = (const float*)d_in[4];
    const float* b2    = (const float*)d_in[5];
    const float* beta2 = (const float*)d_in[6];
    const float* W3    = (const float*)d_in[7];
    const float* b3    = (const float*)d_in[8];
    const float* beta3 = (const float*)d_in[9];
    const float* W4    = (const float*)d_in[10];
    const float* b4    = (const float*)d_in[11];
    float* out = (float*)d_out;

    int Brows = in_sizes[0] / (G_ * S_);   // 16384

    size_t smem_bytes = (size_t)SMEM_FLOATS * sizeof(float);  // ~133 KB
    // Idempotent, deterministic, no allocation; safe before/during capture.
    cudaFuncSetAttribute(gmlp_fused_kernel,
                         cudaFuncAttributeMaxDynamicSharedMemorySize,
                         (int)smem_bytes);

    dim3 grid(Brows / TB, G_);
    gmlp_fused_kernel<<<grid, NT, smem_bytes>>>(
        x, W1, b1, beta1, W2, b2, beta2, W3, b3, beta3, W4, b4, out);
}

// round 5
// speedup vs baseline: 2.7168x; 2.7168x over previous
#include <cuda_runtime.h>
#include <cuda_bf16.h>
#include <stdint.h>
#include <math.h>

#define G_    8
#define S_    16
#define H_    512
#define BM    64          // rows per CTA
#define NT    256         // threads per CTA

// ---------------- device weight scratch (static, allowed) ----------------
__device__ __nv_bfloat16 g_W2hi[G_*H_*H_];
__device__ __nv_bfloat16 g_W2lo[G_*H_*H_];
__device__ __nv_bfloat16 g_W3hi[G_*H_*H_];
__device__ __nv_bfloat16 g_W3lo[G_*H_*H_];

// ---------------- smem layout (bytes) ----------------
// AHI [64][256] u32 pairs : 0      .. 65536
// ALO                      : 65536  .. 131072
// BBUF 2 x 32KB            : 131072 .. 196608   (also W4t+stage overlay in layer4)
// XS  [64][20] f32         : 196608 .. 201728
// BL  [512] f32            : 201728 .. 203776
#define SM_AHI  0
#define SM_ALO  65536
#define SM_B    131072
#define SM_XS   196608
#define SM_BL   201728
#define SMEM_BYTES 203776

// ---------------- helpers ----------------
__device__ __forceinline__ float swishf(float v, float sp) {
    return v * __fdividef(1.0f, 1.0f + __expf(-v * sp)) * (1.0f / 1.1f);
}
__device__ __forceinline__ float softplusf(float b) { return log1pf(__expf(b)); }

// pack two floats -> bf16x2 (lo_elem in low 16 bits)
__device__ __forceinline__ uint32_t bf16pair(float lo_elem, float hi_elem) {
    uint32_t r;
    asm("cvt.rn.bf16x2.f32 %0, %1, %2;" : "=r"(r) : "f"(hi_elem), "f"(lo_elem));
    return r;
}

// swizzled u32-pair index helpers (conflict-free for m16n8k16 frag access)
__device__ __forceinline__ int a_idx(int r, int p) { return r * 256 + (p ^ ((r & 7) << 2)); }
__device__ __forceinline__ int b_idx(int n, int p) { return n * 16  + (p ^ (((n >> 1) & 3) << 2)); }

__device__ __forceinline__ void mma16816(float* c,
    uint32_t a0, uint32_t a1, uint32_t a2, uint32_t a3, uint32_t b0, uint32_t b1) {
    asm volatile(
        "mma.sync.aligned.m16n8k16.row.col.f32.bf16.bf16.f32 "
        "{%0,%1,%2,%3},{%4,%5,%6,%7},{%8,%9},{%0,%1,%2,%3};"
        : "+f"(c[0]), "+f"(c[1]), "+f"(c[2]), "+f"(c[3])
        : "r"(a0), "r"(a1), "r"(a2), "r"(a3), "r"(b0), "r"(b1));
}

template<int N> __device__ __forceinline__ void cp_wait() {
    asm volatile("cp.async.wait_group %0;" :: "n"(N) : "memory");
}

// load one B chunk [512 n][32 k] bf16 (32KB) via cp.async, swizzled
__device__ __forceinline__ void load_chunk(uint32_t dst_base, const __nv_bfloat16* Wsrc,
                                           int kc, int tid) {
    #pragma unroll
    for (int l = 0; l < 8; ++l) {
        int j = tid + NT * l;           // 0..2047 16B chunks
        int n = j >> 2, q = j & 3;
        const void* src = Wsrc + (size_t)n * H_ + kc * 32 + q * 8;
        uint32_t dst = dst_base + n * 64 + ((q ^ ((n >> 1) & 3)) << 4);
        asm volatile("cp.async.cg.shared.global [%0], [%1], 16;" :: "r"(dst), "l"(src));
    }
    asm volatile("cp.async.commit_group;" ::: "memory");
}

// mma over one 32-wide k-chunk.  BOTH: run Ah and Al passes (Bh chunk); else Ah only.
template<bool BOTH>
__device__ __forceinline__ void mma_chunk(float (&acc)[2][16][4],
    const uint32_t* Ah, const uint32_t* Al, const uint32_t* Bp,
    int kc, int wm, int wn, int gq, int t) {
    #pragma unroll
    for (int kk = 0; kk < 2; ++kk) {
        uint32_t B0[16], B1[16];
        #pragma unroll
        for (int ni = 0; ni < 16; ++ni) {
            int n = wn * 128 + ni * 8 + gq;
            B0[ni] = Bp[b_idx(n, kk * 8 + t)];
            B1[ni] = Bp[b_idx(n, kk * 8 + 4 + t)];
        }
        int pb = kc * 16 + kk * 8;
        #pragma unroll
        for (int mi = 0; mi < 2; ++mi) {
            int r = wm * 32 + mi * 16;
            uint32_t a0 = Ah[a_idx(r + gq,     pb + t)];
            uint32_t a1 = Ah[a_idx(r + 8 + gq, pb + t)];
            uint32_t a2 = Ah[a_idx(r + gq,     pb + 4 + t)];
            uint32_t a3 = Ah[a_idx(r + 8 + gq, pb + 4 + t)];
            #pragma unroll
            for (int ni = 0; ni < 16; ++ni) mma16816(acc[mi][ni], a0, a1, a2, a3, B0[ni], B1[ni]);
        }
        if (BOTH) {
            #pragma unroll
            for (int mi = 0; mi < 2; ++mi) {
                int r = wm * 32 + mi * 16;
                uint32_t a0 = Al[a_idx(r + gq,     pb + t)];
                uint32_t a1 = Al[a_idx(r + 8 + gq, pb + t)];
                uint32_t a2 = Al[a_idx(r + gq,     pb + 4 + t)];
                uint32_t a3 = Al[a_idx(r + 8 + gq, pb + 4 + t)];
                #pragma unroll
                for (int ni = 0; ni < 16; ++ni) mma16816(acc[mi][ni], a0, a1, a2, a3, B0[ni], B1[ni]);
            }
        }
    }
}

// ---------------- prep: split W2/W3 into bf16 hi/lo ----------------
__global__ void prep_kernel(const float* __restrict__ W2, const float* __restrict__ W3) {
    const int n = G_ * H_ * H_;
    for (int i = blockIdx.x * blockDim.x + threadIdx.x; i < n; i += gridDim.x * blockDim.x) {
        float w = W2[i];
        __nv_bfloat16 h = __float2bfloat16(w);
        g_W2hi[i] = h;
        g_W2lo[i] = __float2bfloat16(w - __bfloat162float(h));
        w = W3[i];
        h = __float2bfloat16(w);
        g_W3hi[i] = h;
        g_W3lo[i] = __float2bfloat16(w - __bfloat162float(h));
    }
}

// ---------------- fused kernel ----------------
__global__ void __launch_bounds__(NT, 1) fused_kernel(
    const float* __restrict__ x,
    const float* __restrict__ W1, const float* __restrict__ b1, const float* __restrict__ beta1,
    const float* __restrict__ b2, const float* __restrict__ beta2,
    const float* __restrict__ b3, const float* __restrict__ beta3,
    const float* __restrict__ W4, const float* __restrict__ b4,
    float* __restrict__ out)
{
    extern __shared__ char sm[];
    uint32_t* Ah = (uint32_t*)(sm + SM_AHI);
    uint32_t* Al = (uint32_t*)(sm + SM_ALO);
    char*     Bb = sm + SM_B;
    float*    xs = (float*)(sm + SM_XS);
    float*    bL = (float*)(sm + SM_BL);
    const uint32_t smB = (uint32_t)__cvta_generic_to_shared(Bb);

    const int tid = threadIdx.x, wid = tid >> 5, lane = tid & 31;
    const int g  = blockIdx.y;
    const int b0 = blockIdx.x * BM;
    const int wm = wid >> 2, wn = wid & 3;       // warp grid 2x4
    const int gq = lane >> 2, t = lane & 3;       // mma group / thread-in-group

    // ---- stage x tile [64x16] (stride 20 for bank spread) ----
    for (int i = tid; i < BM * S_; i += NT) {
        int r = i >> 4, s = i & 15;
        xs[r * 20 + s] = x[(size_t)(b0 + r) * (G_ * S_) + g * S_ + s];
    }
    __syncthreads();

    // ================= layer 1 (fp32 SIMT) -> Ah/Al =================
    {
        const float sp1 = softplusf(beta1[g]);
        const int c0 = tid * 2;
        const float* w0 = W1 + ((size_t)g * H_ + c0) * S_;   // rows c0, c0+1 contiguous
        float wreg[32];
        #pragma unroll
        for (int q = 0; q < 8; ++q) {
            float4 v = *(const float4*)(w0 + q * 4);
            wreg[q * 4 + 0] = v.x; wreg[q * 4 + 1] = v.y;
            wreg[q * 4 + 2] = v.z; wreg[q * 4 + 3] = v.w;
        }
        const float bb0 = b1[(size_t)g * H_ + c0];
        const float bb1 = b1[(size_t)g * H_ + c0 + 1];
        for (int r = 0; r < BM; ++r) {
            const float* xr = xs + r * 20;
            float4 xa = *(const float4*)(xr);
            float4 xb = *(const float4*)(xr + 4);
            float4 xc = *(const float4*)(xr + 8);
            float4 xd = *(const float4*)(xr + 12);
            float xv[16] = {xa.x, xa.y, xa.z, xa.w, xb.x, xb.y, xb.z, xb.w,
                            xc.x, xc.y, xc.z, xc.w, xd.x, xd.y, xd.z, xd.w};
            float v0 = bb0, v1 = bb1;
            #pragma unroll
            for (int s = 0; s < 16; ++s) {
                v0 = fmaf(xv[s], wreg[s],      v0);
                v1 = fmaf(xv[s], wreg[16 + s], v1);
            }
            v0 = swishf(v0, sp1);
            v1 = swishf(v1, sp1);
            uint32_t hp = bf16pair(v0, v1);
            float h0 = __uint_as_float(hp << 16);
            float h1 = __uint_as_float(hp & 0xffff0000u);
            uint32_t lp = bf16pair(v0 - h0, v1 - h1);
            int ai = a_idx(r, tid);
            Ah[ai] = hp;
            Al[ai] = lp;
        }
    }
    __syncthreads();

    float acc[2][16][4];

    // ================= layers 2 & 3 (bf16 3-pass HMMA) =================
    #pragma unroll 1
    for (int layer = 0; layer < 2; ++layer) {
        const __nv_bfloat16* Whi = (layer == 0 ? g_W2hi : g_W3hi) + (size_t)g * H_ * H_;
        const __nv_bfloat16* Wlo = (layer == 0 ? g_W2lo : g_W3lo) + (size_t)g * H_ * H_;
        const float* bg   = (layer == 0 ? b2 : b3) + (size_t)g * H_;
        const float  sp   = softplusf(layer == 0 ? beta2[g] : beta3[g]);

        // stage bias (A-write of prev layer already barriered)
        bL[tid]       = bg[tid];
        bL[tid + 256] = bg[tid + 256];

        #pragma unroll
        for (int mi = 0; mi < 2; ++mi)
            #pragma unroll
            for (int ni = 0; ni < 16; ++ni)
                #pragma unroll
                for (int q = 0; q < 4; ++q) acc[mi][ni][q] = 0.0f;

        // chunk sequence: i even -> Bhi(kc=i/2) [both A passes], i odd -> Blo(kc) [Ah pass]
        load_chunk(smB, Whi, 0, tid);
        #pragma unroll 1
        for (int i = 0; i < 32; ++i) {
            int cur = (i & 1) * 32768;              // buffer alternates every chunk
            if (i < 31) {
                int kc = (i + 1) >> 1;
                const __nv_bfloat16* W = ((i + 1) & 1) ? Wlo : Whi;
                load_chunk(smB + (((i + 1) & 1) * 32768), W, kc, tid);
                cp_wait<1>();
            } else {
                cp_wait<0>();
            }
            __syncthreads();
            const uint32_t* Bp = (const uint32_t*)(Bb + cur);
            if ((i & 1) == 0) mma_chunk<true >(acc, Ah, Al, Bp, i >> 1, wm, wn, gq, t);
            else              mma_chunk<false>(acc, Ah, Al, Bp, i >> 1, wm, wn, gq, t);
            __syncthreads();
        }

        if (layer == 0) {
            // epilogue: swish -> hi/lo split -> overwrite Ah/Al in place
            #pragma unroll
            for (int mi = 0; mi < 2; ++mi) {
                #pragma unroll
                for (int ni = 0; ni < 16; ++ni) {
                    int cb = wn * 128 + ni * 8 + 2 * t;
                    float be = bL[cb], bo = bL[cb + 1];
                    float v00 = swishf(acc[mi][ni][0] + be, sp);
                    float v01 = swishf(acc[mi][ni][1] + bo, sp);
                    float v10 = swishf(acc[mi][ni][2] + be, sp);
                    float v11 = swishf(acc[mi][ni][3] + bo, sp);
                    int p  = wn * 64 + ni * 4 + t;
                    int r0 = wm * 32 + mi * 16 + gq;
                    uint32_t hp0 = bf16pair(v00, v01);
                    float h0 = __uint_as_float(hp0 << 16);
                    float h1 = __uint_as_float(hp0 & 0xffff0000u);
                    uint32_t lp0 = bf16pair(v00 - h0, v01 - h1);
                    int ai0 = a_idx(r0, p);
                    Ah[ai0] = hp0; Al[ai0] = lp0;
                    uint32_t hp1 = bf16pair(v10, v11);
                    float h2 = __uint_as_float(hp1 << 16);
                    float h3 = __uint_as_float(hp1 & 0xffff0000u);
                    uint32_t lp1 = bf16pair(v10 - h2, v11 - h3);
                    int ai1 = a_idx(r0 + 8, p);
                    Ah[ai1] = hp1; Al[ai1] = lp1;
                }
            }
            __syncthreads();
        } else {
            // layer-3 epilogue: swish in registers (h3 stays in acc)
            #pragma unroll
            for (int mi = 0; mi < 2; ++mi) {
                #pragma unroll
                for (int ni = 0; ni < 16; ++ni) {
                    int cb = wn * 128 + ni * 8 + 2 * t;
                    float be = bL[cb], bo = bL[cb + 1];
                    acc[mi][ni][0] = swishf(acc[mi][ni][0] + be, sp);
                    acc[mi][ni][1] = swishf(acc[mi][ni][1] + bo, sp);
                    acc[mi][ni][2] = swishf(acc[mi][ni][2] + be, sp);
                    acc[mi][ni][3] = swishf(acc[mi][ni][3] + bo, sp);
                }
            }
        }
    }

    // ================= layer 4 (fp32 SIMT from registers) =================
    {
        // stage W4^T [512][20] f32 into (now free) B region
        float* W4t = (float*)Bb;
        const float* W4g = W4 + (size_t)g * S_ * H_;
        for (int i = tid; i < H_ * S_; i += NT) {
            int c = i & 511, s = i >> 9;
            W4t[c * 20 + s] = W4g[(size_t)s * H_ + c];
        }
        __syncthreads();

        float pacc[2][2][16];    // [mi][g-half][s]
        #pragma unroll
        for (int a = 0; a < 2; ++a)
            #pragma unroll
            for (int bq = 0; bq < 2; ++bq)
                #pragma unroll
                for (int s = 0; s < 16; ++s) pacc[a][bq][s] = 0.0f;

        #pragma unroll
        for (int ni = 0; ni < 16; ++ni) {
            int ce = wn * 128 + ni * 8 + 2 * t;
            float we[16], wo[16];
            #pragma unroll
            for (int q = 0; q < 4; ++q) {
                float4 v = *(const float4*)(W4t + ce * 20 + q * 4);
                we[q*4+0] = v.x; we[q*4+1] = v.y; we[q*4+2] = v.z; we[q*4+3] = v.w;
                float4 u = *(const float4*)(W4t + (ce + 1) * 20 + q * 4);
                wo[q*4+0] = u.x; wo[q*4+1] = u.y; wo[q*4+2] = u.z; wo[q*4+3] = u.w;
            }
            #pragma unroll
            for (int mi = 0; mi < 2; ++mi) {
                float h00 = acc[mi][ni][0], h01 = acc[mi][ni][1];
                float h10 = acc[mi][ni][2], h11 = acc[mi][ni][3];
                #pragma unroll
                for (int s = 0; s < 16; ++s) {
                    pacc[mi][0][s] = fmaf(h00, we[s], fmaf(h01, wo[s], pacc[mi][0][s]));
                    pacc[mi][1][s] = fmaf(h10, we[s], fmaf(h11, wo[s], pacc[mi][1][s]));
                }
            }
        }
        // reduce over the 4 t-lanes
        #pragma unroll
        for (int mi = 0; mi < 2; ++mi)
            #pragma unroll
            for (int bq = 0; bq < 2; ++bq)
                #pragma unroll
                for (int s = 0; s < 16; ++s) {
                    float v = pacc[mi][bq][s];
                    v += __shfl_xor_sync(0xffffffffu, v, 1);
                    v += __shfl_xor_sync(0xffffffffu, v, 2);
                    pacc[mi][bq][s] = v;
                }
        // stage per-warp_n partials: [4][64][16] f32 (16KB) after W4t (40KB) in B region
        float* stg = (float*)(Bb + 40960);
        if (t == 0) {
            #pragma unroll
            for (int mi = 0; mi < 2; ++mi)
                #pragma unroll
                for (int bq = 0; bq < 2; ++bq) {
                    int r = wm * 32 + mi * 16 + bq * 8 + gq;
                    #pragma unroll
                    for (int s = 0; s < 16; ++s)
                        stg[(wn * 64 + r) * 16 + s] = pacc[mi][bq][s];
                }
        }
        __syncthreads();
        // final: sum 4 warp_n partials + b4, write out
        {
            int r = tid >> 2, s0 = (tid & 3) * 4;
            float o[4];
            #pragma unroll
            for (int q = 0; q < 4; ++q) o[q] = b4[(size_t)g * S_ + s0 + q];
            #pragma unroll
            for (int w = 0; w < 4; ++w) {
                float4 v = *(const float4*)(stg + (w * 64 + r) * 16 + s0);
                o[0] += v.x; o[1] += v.y; o[2] += v.z; o[3] += v.w;
            }
            *(float4*)&out[(size_t)(b0 + r) * (G_ * S_) + g * S_ + s0] =
                make_float4(o[0], o[1], o[2], o[3]);
        }
    }
}

// ================= launch =================
extern "C" void kernel_launch(void* const* d_in, const int* in_sizes, int n_in,
                              void* d_out, int out_size) {
    const float* x     = (const float*)d_in[0];
    const float* W1    = (const float*)d_in[1];
    const float* b1    = (const float*)d_in[2];
    const float* beta1 = (const float*)d_in[3];
    const float* W2    = (const float*)d_in[4];
    const float* b2    = (const float*)d_in[5];
    const float* beta2 = (const float*)d_in[6];
    const float* W3    = (const float*)d_in[7];
    const float* b3    = (const float*)d_in[8];
    const float* beta3 = (const float*)d_in[9];
    const float* W4    = (const float*)d_in[10];
    const float* b4    = (const float*)d_in[11];
    float* out = (float*)d_out;

    int Brows = in_sizes[0] / (G_ * S_);

    cudaFuncSetAttribute(fused_kernel, cudaFuncAttributeMaxDynamicSharedMemorySize, SMEM_BYTES);

    prep_kernel<<<512, 256>>>(W2, W3);

    dim3 grid(Brows / BM, G_);
    fused_kernel<<<grid, NT, SMEM_BYTES>>>(x, W1, b1, beta1, b2, beta2, b3, beta3, W4, b4, out);
}